// round 13
// baseline (speedup 1.0000x reference)
#include <cuda_runtime.h>
#include <cuda_bf16.h>

// PerformerHead: algebraic reduction.
// Causal linear attention output at position 0 equals v at position 0 exactly
// (attn[0,0]*v0 / attn[0,0]); the final classifier reads only h[:,0,:].
// Per batch the model reduces to a 256-dim vector through 4 residual blocks:
//   h += LN1(h) @ wv @ wo + bo
//   h += gelu(LN2(h) @ w1 + b1) @ w2 + b2
// seeded with emb_tok[x[b,0]] + emb_pos[0], then h @ w_cls + b_cls.
//
// Round-2 optimization (resubmitted; broker timeouts R2-R12): latency-bound
// (DRAM 0.7%, issue 18.6%). All matvecs use float4 weight loads + deep
// K-split + warp-shuffle reduction to cut dependent L2-latency batches ~4x.

#define DM 256
#define DH 1024
#define NL 4
#define NT 1024

// Fused two-value block sum over 1024 threads (32 warps).
__device__ __forceinline__ float2 blocksum2(float a, float b, float* red) {
    #pragma unroll
    for (int o = 16; o > 0; o >>= 1) {
        a += __shfl_xor_sync(0xffffffffu, a, o);
        b += __shfl_xor_sync(0xffffffffu, b, o);
    }
    const int lane = threadIdx.x & 31, w = threadIdx.x >> 5;
    if (lane == 0) { red[w] = a; red[32 + w] = b; }
    __syncthreads();
    if (w == 0) {
        float s1 = red[lane], s2 = red[32 + lane];
        #pragma unroll
        for (int o = 16; o > 0; o >>= 1) {
            s1 += __shfl_xor_sync(0xffffffffu, s1, o);
            s2 += __shfl_xor_sync(0xffffffffu, s2, o);
        }
        if (lane == 0) { red[0] = s1; red[32] = s2; }
    }
    __syncthreads();
    float2 r = make_float2(red[0], red[32]);
    __syncthreads();
    return r;
}

// y = LN(h) * s + b  (eps 1e-5). Single fused reduction: var = E[x^2]-mu^2.
__device__ __forceinline__ void layernorm(const float* __restrict__ h,
                                          float* __restrict__ y,
                                          const float* __restrict__ s,
                                          const float* __restrict__ b,
                                          float* red, int t) {
    float xv = (t < DM) ? h[t] : 0.0f;
    float2 ss = blocksum2(xv, xv * xv, red);
    float mu  = ss.x * (1.0f / DM);
    float var = ss.y * (1.0f / DM) - mu * mu;
    float inv = rsqrtf(var + 1e-5f);
    if (t < DM) y[t] = (xv - mu) * inv * s[t] + b[t];
    __syncthreads();
}

// 256->256 matvec. Thread t: group g=t/16 owns output cols 4g..4g+3 (float4),
// sub=t%16 owns K rows [16*sub,16*sub+16). Shuffle-reduce over sub.
// mode 0: out4[g] = r        (no bias)
// mode 2: out4[g] += r + bias (residual accumulate into h)
template <int MODE>
__device__ __forceinline__ void mv256(const float* __restrict__ in,
                                      const float* __restrict__ W,
                                      const float* __restrict__ bias,
                                      float4* __restrict__ out4, int t) {
    const int g = t >> 4, sub = t & 15;
    const float4* Wp = reinterpret_cast<const float4*>(W) + (size_t)(sub * 16) * 64 + g;
    const float* ip = in + sub * 16;
    float4 acc = make_float4(0.f, 0.f, 0.f, 0.f);
    #pragma unroll 8
    for (int i = 0; i < 16; i++) {
        float s = ip[i];
        float4 w = Wp[(size_t)i * 64];
        acc.x += s * w.x; acc.y += s * w.y; acc.z += s * w.z; acc.w += s * w.w;
    }
    #pragma unroll
    for (int o = 8; o > 0; o >>= 1) {
        acc.x += __shfl_xor_sync(0xffffffffu, acc.x, o);
        acc.y += __shfl_xor_sync(0xffffffffu, acc.y, o);
        acc.z += __shfl_xor_sync(0xffffffffu, acc.z, o);
        acc.w += __shfl_xor_sync(0xffffffffu, acc.w, o);
    }
    if (sub == 0) {
        if (MODE >= 1) {
            float4 bb = reinterpret_cast<const float4*>(bias)[g];
            acc.x += bb.x; acc.y += bb.y; acc.z += bb.z; acc.w += bb.w;
        }
        if (MODE == 2) {
            float4 o0 = out4[g];
            acc.x += o0.x; acc.y += o0.y; acc.z += o0.z; acc.w += o0.w;
        }
        out4[g] = acc;
    }
    __syncthreads();
}

__device__ __forceinline__ float gelu_t(float a) {
    const float k0 = 0.7978845608028654f;   // sqrt(2/pi)
    return 0.5f * a * (1.0f + tanhf(k0 * (a + 0.044715f * a * a * a)));
}

__global__ __launch_bounds__(NT, 1)
void performer_tok0_kernel(const int* __restrict__ x, int N,
                           const float* __restrict__ emb_tok,
                           const float* __restrict__ emb_pos,
                           const float* __restrict__ ln1_s,
                           const float* __restrict__ ln1_b,
                           const float* __restrict__ wv,
                           const float* __restrict__ wo,
                           const float* __restrict__ bo,
                           const float* __restrict__ ln2_s,
                           const float* __restrict__ ln2_b,
                           const float* __restrict__ w1,
                           const float* __restrict__ b1,
                           const float* __restrict__ w2,
                           const float* __restrict__ b2,
                           const float* __restrict__ wcls,
                           const float* __restrict__ bcls,
                           float* __restrict__ out) {
    __shared__ __align__(16) float h[DM];
    __shared__ __align__(16) float y[DM];
    __shared__ __align__(16) float u[DH];
    __shared__ float red[64];

    const int t = threadIdx.x;
    const int bidx = blockIdx.x;

    if (t < DM) {
        const int tok = x[(size_t)bidx * N];   // x[b, 0]
        h[t] = emb_tok[(size_t)tok * DM + t] + emb_pos[t];
    }
    __syncthreads();

    for (int l = 0; l < NL; l++) {
        const float* Wv = wv + (size_t)l * DM * DM;
        const float* Wo = wo + (size_t)l * DM * DM;
        const float* W1 = w1 + (size_t)l * DM * DH;
        const float* W2 = w2 + (size_t)l * DH * DM;

        // ---- attention path (reduced): h += LN1(h) @ Wv @ Wo + bo ----
        layernorm(h, y, ln1_s + l * DM, ln1_b + l * DM, red, t);
        mv256<0>(y, Wv, nullptr, (float4*)u, t);                 // v0
        mv256<2>(u, Wo, bo + l * DM, (float4*)h, t);             // h += o0

        // ---- MLP: h += gelu(LN2(h) @ W1 + b1) @ W2 + b2 ----
        layernorm(h, y, ln2_s + l * DM, ln2_b + l * DM, red, t);
        {
            // 1024 outputs: group g=t/4 owns cols 4g..4g+3, sub=t%4 owns 64 K rows.
            const int g = t >> 2, sub = t & 3;
            const float4* Wp = reinterpret_cast<const float4*>(W1) + (size_t)(sub * 64) * 256 + g;
            const float* ip = y + sub * 64;
            float4 acc = make_float4(0.f, 0.f, 0.f, 0.f);
            #pragma unroll 8
            for (int i = 0; i < 64; i++) {
                float s = ip[i];
                float4 w = Wp[(size_t)i * 256];
                acc.x += s * w.x; acc.y += s * w.y; acc.z += s * w.z; acc.w += s * w.w;
            }
            #pragma unroll
            for (int o = 2; o > 0; o >>= 1) {
                acc.x += __shfl_xor_sync(0xffffffffu, acc.x, o);
                acc.y += __shfl_xor_sync(0xffffffffu, acc.y, o);
                acc.z += __shfl_xor_sync(0xffffffffu, acc.z, o);
                acc.w += __shfl_xor_sync(0xffffffffu, acc.w, o);
            }
            if (sub == 0) {
                float4 bb = reinterpret_cast<const float4*>(b1 + l * DH)[g];
                float4 r;
                r.x = gelu_t(acc.x + bb.x);
                r.y = gelu_t(acc.y + bb.y);
                r.z = gelu_t(acc.z + bb.z);
                r.w = gelu_t(acc.w + bb.w);
                reinterpret_cast<float4*>(u)[g] = r;
            }
            __syncthreads();
        }
        {
            // 256 outputs, K=1024: group g=t/16 owns cols 4g..4g+3, sub=t%16 owns 64 K rows.
            const int g = t >> 4, sub = t & 15;
            const float4* Wp = reinterpret_cast<const float4*>(W2) + (size_t)(sub * 64) * 64 + g;
            const float* ip = u + sub * 64;
            float4 acc = make_float4(0.f, 0.f, 0.f, 0.f);
            #pragma unroll 8
            for (int i = 0; i < 64; i++) {
                float s = ip[i];
                float4 w = Wp[(size_t)i * 64];
                acc.x += s * w.x; acc.y += s * w.y; acc.z += s * w.z; acc.w += s * w.w;
            }
            #pragma unroll
            for (int o = 8; o > 0; o >>= 1) {
                acc.x += __shfl_xor_sync(0xffffffffu, acc.x, o);
                acc.y += __shfl_xor_sync(0xffffffffu, acc.y, o);
                acc.z += __shfl_xor_sync(0xffffffffu, acc.z, o);
                acc.w += __shfl_xor_sync(0xffffffffu, acc.w, o);
            }
            if (sub == 0) {
                float4 bb = reinterpret_cast<const float4*>(b2 + l * DM)[g];
                float4* h4 = reinterpret_cast<float4*>(h);
                float4 o0 = h4[g];
                o0.x += acc.x + bb.x; o0.y += acc.y + bb.y;
                o0.z += acc.z + bb.z; o0.w += acc.w + bb.w;
                h4[g] = o0;
            }
            __syncthreads();
        }
    }

    // ---- classifier head: out[b] = h @ wcls + bcls (C=10). Warp j -> output j.
    if (t < 320) {
        const int j = t >> 5, lane = t & 31;
        float acc = 0.0f;
        #pragma unroll
        for (int i = 0; i < 8; i++)
            acc += h[lane * 8 + i] * wcls[(size_t)(lane * 8 + i) * 10 + j];
        #pragma unroll
        for (int o = 16; o > 0; o >>= 1) acc += __shfl_xor_sync(0xffffffffu, acc, o);
        if (lane == 0) out[(size_t)bidx * 10 + j] = acc + bcls[j];
    }
}

extern "C" void kernel_launch(void* const* d_in, const int* in_sizes, int n_in,
                              void* d_out, int out_size) {
    // 0:x 1:emb_tok 2:emb_pos 3:proj(unused) 4:ln1_s 5:ln1_b 6:wq(unused)
    // 7:wk(unused) 8:wv 9:wo 10:bo 11:ln2_s 12:ln2_b 13:w1 14:b1 15:w2 16:b2
    // 17:w_cls 18:b_cls
    const int*   x       = (const int*)  d_in[0];
    const float* emb_tok = (const float*)d_in[1];
    const float* emb_pos = (const float*)d_in[2];
    const float* ln1_s   = (const float*)d_in[4];
    const float* ln1_b   = (const float*)d_in[5];
    const float* wv      = (const float*)d_in[8];
    const float* wo      = (const float*)d_in[9];
    const float* bo      = (const float*)d_in[10];
    const float* ln2_s   = (const float*)d_in[11];
    const float* ln2_b   = (const float*)d_in[12];
    const float* w1      = (const float*)d_in[13];
    const float* b1      = (const float*)d_in[14];
    const float* w2      = (const float*)d_in[15];
    const float* b2      = (const float*)d_in[16];
    const float* wcls    = (const float*)d_in[17];
    const float* bcls    = (const float*)d_in[18];
    float* out = (float*)d_out;

    const int B = out_size / 10;          // 16
    const int N = in_sizes[0] / B;        // 4096

    performer_tok0_kernel<<<B, NT>>>(x, N, emb_tok, emb_pos,
                                     ln1_s, ln1_b, wv, wo, bo,
                                     ln2_s, ln2_b, w1, b1, w2, b2,
                                     wcls, bcls, out);
    (void)n_in;
}